// round 8
// baseline (speedup 1.0000x reference)
#include <cuda_runtime.h>

// Lyapunov spectrum for the Lorenz-Jacobian + row Gram-Schmidt reference.
//
// KEY IDENTITY: the reference's Q_t is row-orthonormal after every GS step,
// so the Gram matrix of M = (I+DT*J)Q_{t-1} is
//     S = M M^T = A (Q Q^T) A^T = A A^T,  A = I + DT*J(x,y,z),
// a pure function of the input sample (x,y,z). The outputs (log norms of the
// GS residuals) are functions of S only:
//     |r0|^2 = s00 = 0.82                   (compile-time constant)
//     |r1|^2 = s11 - s01^2/s00              = u11
//     |r2|^2 = s22 - t02^2 - u12^2/u11      = v22
// Q never materializes: the problem is an elementwise map over (T, B) plus a
// sum over T -> HBM-bound streaming reduction (201 MB read once, ~25-29 us).
//
// float4 loads along B (LDG.128, fully coalesced). Outer loop rolled: live
// set = 2 x 4-step double-buffered groups (~140 regs -> 1 block/SM). 1024
// blocks (G_CHUNK=128) so the reg-limited 1-block/SM schedule has <1% wave
// tail (512 blocks had a 68/148 final wave, ~3-4% loss).
//
// Pass 1: partial sums to a 16 MB __device__ scratch (no atomics,
//         deterministic, graph-capturable).  Pass 2: reduce + scale.

#define T_STEPS 2048
#define BATCH   8192
#define ROWS4   (BATCH / 4)           // 2048 float4 per component row
#define G_CHUNK 128
#define CHUNK_T (T_STEPS / G_CHUNK)   // 16 steps per chunk

#define DTf     0.01f
#define S11c    0.98010004f          // 0.99^2
#define S22c    0.94737780f          // A22^2
#define S12c    0.016666668f         // 0.99 - A22
#define T01ac   0.99388373f          // 0.9/sqrt(0.82)
#define T01bc   0.10932722f          // 0.099/sqrt(0.82)
#define T02ac   0.11043153f          // 0.1/sqrt(0.82)
#define LAM0c  -9.9225469f           // 0.5*ln(0.82)/DT

__device__ float4 g_partials[G_CHUNK * 2 * ROWS4];   // 16 MB scratch

__device__ __forceinline__ float frcp_approx(float v) {
    float r;
    asm("rcp.approx.f32 %0, %1;" : "=f"(r) : "f"(v));
    return r;
}

// squared GS residual norms (u11, v22) of one input sample
__device__ __forceinline__ void norms_from_sample(float x, float y, float z,
                                                  float &u11, float &v22)
{
    float c1 = fmaf(-DTf, z, 0.28f);       // DT*(28 - z)
    float cx = DTf * x;
    float cy = DTf * y;

    float cxsq = cx * cx;
    float s11  = fmaf(c1, c1, S11c + cxsq);
    float s12  = fmaf(c1, cy, S12c * cx);
    float s22  = fmaf(cy, cy, S22c + cxsq);

    // t0k = (q0' . m_k) with 1/sqrt(0.82) folded into the constants
    float t01 = fmaf(c1, T01ac, T01bc);
    float t02 = fmaf(cy, T01ac, T02ac * cx);

    u11 = fmaf(-t01, t01, s11);
    float u12 = fmaf(-t01, t02, s12);
    float u22 = fmaf(-t02, t02, s22);
    float w1  = frcp_approx(u11);
    v22 = fmaf(-u12 * u12, w1, u22);
}

// one time-step for 4 batch lanes
__device__ __forceinline__ void step4(const float4 &x, const float4 &y,
                                      const float4 &z,
                                      float4 &pl1, float4 &pl2)
{
    float u, v;
    norms_from_sample(x.x, y.x, z.x, u, v); pl1.x *= u; pl2.x *= v;
    norms_from_sample(x.y, y.y, z.y, u, v); pl1.y *= u; pl2.y *= v;
    norms_from_sample(x.z, y.z, z.z, u, v); pl1.z *= u; pl2.z *= v;
    norms_from_sample(x.w, y.w, z.w, u, v); pl1.w *= u; pl2.w *= v;
}

#define LOAD_GROUP(bx, by, bz, g)                                              \
    _Pragma("unroll")                                                          \
    for (int i = 0; i < 4; i++) {                                              \
        const float4* q = p + (size_t)((g) * 4 + i) * 3 * ROWS4;               \
        bx[i] = __ldcs(q);                                                     \
        by[i] = __ldcs(q + ROWS4);                                             \
        bz[i] = __ldcs(q + 2 * ROWS4);                                         \
    }

__global__ __launch_bounds__(256)
void lya_partials_kernel(const float4* __restrict__ traj4)
{
    const int tb    = blockIdx.x * 256 + threadIdx.x;   // 0 .. ROWS4-1
    const int chunk = blockIdx.y;
    const float4* p = traj4 + (size_t)chunk * CHUNK_T * 3 * ROWS4 + tb;

    float4 l1 = make_float4(0.f, 0.f, 0.f, 0.f);
    float4 l2 = make_float4(0.f, 0.f, 0.f, 0.f);

    float4 xa[4], ya[4], za[4], xb[4], yb[4], zb[4];
    const int NG = CHUNK_T / 4;                         // 4 groups of 4 steps

    LOAD_GROUP(xa, ya, za, 0)

    // steady state: branch-clean, double-buffered
#pragma unroll 1
    for (int g = 0; g < NG - 2; g += 2) {
        float4 pl1 = make_float4(1.f, 1.f, 1.f, 1.f);
        float4 pl2 = make_float4(1.f, 1.f, 1.f, 1.f);

        LOAD_GROUP(xb, yb, zb, g + 1)
#pragma unroll
        for (int i = 0; i < 4; i++) step4(xa[i], ya[i], za[i], pl1, pl2);

        LOAD_GROUP(xa, ya, za, g + 2)
#pragma unroll
        for (int i = 0; i < 4; i++) step4(xb[i], yb[i], zb[i], pl1, pl2);

        // one log per 8 steps per lane (product range ~[0.3, 1.5]^8, safe)
        l1.x += __log2f(pl1.x); l1.y += __log2f(pl1.y);
        l1.z += __log2f(pl1.z); l1.w += __log2f(pl1.w);
        l2.x += __log2f(pl2.x); l2.y += __log2f(pl2.y);
        l2.z += __log2f(pl2.z); l2.w += __log2f(pl2.w);
    }

    // epilogue: last two groups
    {
        float4 pl1 = make_float4(1.f, 1.f, 1.f, 1.f);
        float4 pl2 = make_float4(1.f, 1.f, 1.f, 1.f);

        LOAD_GROUP(xb, yb, zb, NG - 1)
#pragma unroll
        for (int i = 0; i < 4; i++) step4(xa[i], ya[i], za[i], pl1, pl2);
#pragma unroll
        for (int i = 0; i < 4; i++) step4(xb[i], yb[i], zb[i], pl1, pl2);

        l1.x += __log2f(pl1.x); l1.y += __log2f(pl1.y);
        l1.z += __log2f(pl1.z); l1.w += __log2f(pl1.w);
        l2.x += __log2f(pl2.x); l2.y += __log2f(pl2.y);
        l2.z += __log2f(pl2.z); l2.w += __log2f(pl2.w);
    }

    g_partials[(chunk * 2 + 0) * ROWS4 + tb] = l1;
    g_partials[(chunk * 2 + 1) * ROWS4 + tb] = l2;
}

__global__ __launch_bounds__(256)
void lya_reduce_kernel(float4* __restrict__ out4)
{
    const int tb = blockIdx.x * 256 + threadIdx.x;      // 0 .. ROWS4-1
    float4 s1 = make_float4(0.f, 0.f, 0.f, 0.f);
    float4 s2 = make_float4(0.f, 0.f, 0.f, 0.f);
#pragma unroll 1
    for (int g = 0; g < G_CHUNK; g++) {
        float4 a = g_partials[(g * 2 + 0) * ROWS4 + tb];
        float4 b = g_partials[(g * 2 + 1) * ROWS4 + tb];
        s1.x += a.x; s1.y += a.y; s1.z += a.z; s1.w += a.w;
        s2.x += b.x; s2.y += b.y; s2.z += b.z; s2.w += b.w;
    }
    // l = sum(log2 n^2) -> lambda = l * 0.5*ln2/(T*DT)
    const float scale = 0.5f * 0.69314718055994531f / (2048.0f * 0.01f);
    out4[tb] = make_float4(LAM0c, LAM0c, LAM0c, LAM0c);
    out4[ROWS4 + tb] = make_float4(s1.x * scale, s1.y * scale,
                                   s1.z * scale, s1.w * scale);
    out4[2 * ROWS4 + tb] = make_float4(s2.x * scale, s2.y * scale,
                                       s2.z * scale, s2.w * scale);
}

extern "C" void kernel_launch(void* const* d_in, const int* in_sizes, int n_in,
                              void* d_out, int out_size)
{
    const float4* traj4 = (const float4*)d_in[0];
    float4* out4 = (float4*)d_out;
    (void)in_sizes; (void)n_in; (void)out_size;

    lya_partials_kernel<<<dim3(ROWS4 / 256, G_CHUNK), 256>>>(traj4);
    lya_reduce_kernel<<<ROWS4 / 256, 256>>>(out4);
}

// round 10
// speedup vs baseline: 1.7370x; 1.7370x over previous
#include <cuda_runtime.h>

// Lyapunov spectrum for the Lorenz-Jacobian + row Gram-Schmidt reference.
//
// KEY IDENTITY: the reference's Q_t is row-orthonormal after every GS step,
// so the Gram matrix of M = (I+DT*J)Q_{t-1} is
//     S = M M^T = A (Q Q^T) A^T = A A^T,  A = I + DT*J(x,y,z),
// a pure function of the input sample (x,y,z). The outputs (log norms of the
// GS residuals) are functions of S only:
//     |r0|^2 = s00 = 0.82                   (compile-time constant)
//     |r1|^2 = s11 - s01^2/s00              = u11
//     |r2|^2 = s22 - t02^2 - u12^2/u11      = v22
// Q never materializes: elementwise map over (T, B) + sum over T.
//
// R8 measured 72.5 us with the REDUCE kernel as bottleneck (grid=8, occ 12%,
// DRAM 1.4% -> latency-bound serial walk of the 16 MB scratch). This round:
// wide reduce -- 64 blocks x (32 tb-lanes x 8 g-slices), 32 independent
// float4 loads per thread (MLP~32), 8-way smem tree, fixed summation order
// (deterministic). Pass 1 unchanged (was not the measured bottleneck).

#define T_STEPS 2048
#define BATCH   8192
#define ROWS4   (BATCH / 4)           // 2048 float4 per component row
#define G_CHUNK 128
#define CHUNK_T (T_STEPS / G_CHUNK)   // 16 steps per chunk

#define DTf     0.01f
#define S11c    0.98010004f          // 0.99^2
#define S22c    0.94737780f          // A22^2
#define S12c    0.016666668f         // 0.99 - A22
#define T01ac   0.99388373f          // 0.9/sqrt(0.82)
#define T01bc   0.10932722f          // 0.099/sqrt(0.82)
#define T02ac   0.11043153f          // 0.1/sqrt(0.82)
#define LAM0c  -9.9225469f           // 0.5*ln(0.82)/DT

__device__ float4 g_partials[G_CHUNK * 2 * ROWS4];   // 16 MB scratch

__device__ __forceinline__ float frcp_approx(float v) {
    float r;
    asm("rcp.approx.f32 %0, %1;" : "=f"(r) : "f"(v));
    return r;
}

// squared GS residual norms (u11, v22) of one input sample
__device__ __forceinline__ void norms_from_sample(float x, float y, float z,
                                                  float &u11, float &v22)
{
    float c1 = fmaf(-DTf, z, 0.28f);       // DT*(28 - z)
    float cx = DTf * x;
    float cy = DTf * y;

    float cxsq = cx * cx;
    float s11  = fmaf(c1, c1, S11c + cxsq);
    float s12  = fmaf(c1, cy, S12c * cx);
    float s22  = fmaf(cy, cy, S22c + cxsq);

    // t0k = (q0' . m_k) with 1/sqrt(0.82) folded into the constants
    float t01 = fmaf(c1, T01ac, T01bc);
    float t02 = fmaf(cy, T01ac, T02ac * cx);

    u11 = fmaf(-t01, t01, s11);
    float u12 = fmaf(-t01, t02, s12);
    float u22 = fmaf(-t02, t02, s22);
    float w1  = frcp_approx(u11);
    v22 = fmaf(-u12 * u12, w1, u22);
}

// one time-step for 4 batch lanes
__device__ __forceinline__ void step4(const float4 &x, const float4 &y,
                                      const float4 &z,
                                      float4 &pl1, float4 &pl2)
{
    float u, v;
    norms_from_sample(x.x, y.x, z.x, u, v); pl1.x *= u; pl2.x *= v;
    norms_from_sample(x.y, y.y, z.y, u, v); pl1.y *= u; pl2.y *= v;
    norms_from_sample(x.z, y.z, z.z, u, v); pl1.z *= u; pl2.z *= v;
    norms_from_sample(x.w, y.w, z.w, u, v); pl1.w *= u; pl2.w *= v;
}

#define LOAD_GROUP(bx, by, bz, g)                                              \
    _Pragma("unroll")                                                          \
    for (int i = 0; i < 4; i++) {                                              \
        const float4* q = p + (size_t)((g) * 4 + i) * 3 * ROWS4;               \
        bx[i] = __ldcs(q);                                                     \
        by[i] = __ldcs(q + ROWS4);                                             \
        bz[i] = __ldcs(q + 2 * ROWS4);                                         \
    }

__global__ __launch_bounds__(256)
void lya_partials_kernel(const float4* __restrict__ traj4)
{
    const int tb    = blockIdx.x * 256 + threadIdx.x;   // 0 .. ROWS4-1
    const int chunk = blockIdx.y;
    const float4* p = traj4 + (size_t)chunk * CHUNK_T * 3 * ROWS4 + tb;

    float4 l1 = make_float4(0.f, 0.f, 0.f, 0.f);
    float4 l2 = make_float4(0.f, 0.f, 0.f, 0.f);

    float4 xa[4], ya[4], za[4], xb[4], yb[4], zb[4];
    const int NG = CHUNK_T / 4;                         // 4 groups of 4 steps

    LOAD_GROUP(xa, ya, za, 0)

    // steady state: branch-clean, double-buffered
#pragma unroll 1
    for (int g = 0; g < NG - 2; g += 2) {
        float4 pl1 = make_float4(1.f, 1.f, 1.f, 1.f);
        float4 pl2 = make_float4(1.f, 1.f, 1.f, 1.f);

        LOAD_GROUP(xb, yb, zb, g + 1)
#pragma unroll
        for (int i = 0; i < 4; i++) step4(xa[i], ya[i], za[i], pl1, pl2);

        LOAD_GROUP(xa, ya, za, g + 2)
#pragma unroll
        for (int i = 0; i < 4; i++) step4(xb[i], yb[i], zb[i], pl1, pl2);

        // one log per 8 steps per lane (product range ~[0.3, 1.5]^8, safe)
        l1.x += __log2f(pl1.x); l1.y += __log2f(pl1.y);
        l1.z += __log2f(pl1.z); l1.w += __log2f(pl1.w);
        l2.x += __log2f(pl2.x); l2.y += __log2f(pl2.y);
        l2.z += __log2f(pl2.z); l2.w += __log2f(pl2.w);
    }

    // epilogue: last two groups
    {
        float4 pl1 = make_float4(1.f, 1.f, 1.f, 1.f);
        float4 pl2 = make_float4(1.f, 1.f, 1.f, 1.f);

        LOAD_GROUP(xb, yb, zb, NG - 1)
#pragma unroll
        for (int i = 0; i < 4; i++) step4(xa[i], ya[i], za[i], pl1, pl2);
#pragma unroll
        for (int i = 0; i < 4; i++) step4(xb[i], yb[i], zb[i], pl1, pl2);

        l1.x += __log2f(pl1.x); l1.y += __log2f(pl1.y);
        l1.z += __log2f(pl1.z); l1.w += __log2f(pl1.w);
        l2.x += __log2f(pl2.x); l2.y += __log2f(pl2.y);
        l2.z += __log2f(pl2.z); l2.w += __log2f(pl2.w);
    }

    g_partials[(chunk * 2 + 0) * ROWS4 + tb] = l1;
    g_partials[(chunk * 2 + 1) * ROWS4 + tb] = l2;
}

// Wide reduce: 64 blocks x (32 tb-lanes x 8 g-slices). Each thread sums
// G_CHUNK/8 = 16 g-values for both components (32 independent float4 loads,
// fully unrolled -> high MLP), then an 8-way smem tree per tb column.
#define RED_GS 8
__global__ __launch_bounds__(32 * RED_GS)
void lya_reduce_kernel(float4* __restrict__ out4)
{
    __shared__ float4 sh1[RED_GS][32];
    __shared__ float4 sh2[RED_GS][32];

    const int lane = threadIdx.x;                    // tb within tile, 0..31
    const int ty   = threadIdx.y;                    // g slice, 0..7
    const int tb   = blockIdx.x * 32 + lane;

    float4 s1 = make_float4(0.f, 0.f, 0.f, 0.f);
    float4 s2 = make_float4(0.f, 0.f, 0.f, 0.f);

#pragma unroll
    for (int k = 0; k < G_CHUNK / RED_GS; k++) {     // 16 iterations
        int g = k * RED_GS + ty;
        float4 a = g_partials[(g * 2 + 0) * ROWS4 + tb];
        float4 b = g_partials[(g * 2 + 1) * ROWS4 + tb];
        s1.x += a.x; s1.y += a.y; s1.z += a.z; s1.w += a.w;
        s2.x += b.x; s2.y += b.y; s2.z += b.z; s2.w += b.w;
    }

    sh1[ty][lane] = s1;
    sh2[ty][lane] = s2;
    __syncthreads();

    if (ty == 0) {
#pragma unroll
        for (int k = 1; k < RED_GS; k++) {
            float4 a = sh1[k][lane];
            float4 b = sh2[k][lane];
            s1.x += a.x; s1.y += a.y; s1.z += a.z; s1.w += a.w;
            s2.x += b.x; s2.y += b.y; s2.z += b.z; s2.w += b.w;
        }
        // l = sum(log2 n^2) -> lambda = l * 0.5*ln2/(T*DT)
        const float scale = 0.5f * 0.69314718055994531f / (2048.0f * 0.01f);
        out4[tb] = make_float4(LAM0c, LAM0c, LAM0c, LAM0c);
        out4[ROWS4 + tb] = make_float4(s1.x * scale, s1.y * scale,
                                       s1.z * scale, s1.w * scale);
        out4[2 * ROWS4 + tb] = make_float4(s2.x * scale, s2.y * scale,
                                           s2.z * scale, s2.w * scale);
    }
}

extern "C" void kernel_launch(void* const* d_in, const int* in_sizes, int n_in,
                              void* d_out, int out_size)
{
    const float4* traj4 = (const float4*)d_in[0];
    float4* out4 = (float4*)d_out;
    (void)in_sizes; (void)n_in; (void)out_size;

    lya_partials_kernel<<<dim3(ROWS4 / 256, G_CHUNK), 256>>>(traj4);
    lya_reduce_kernel<<<ROWS4 / 32, dim3(32, RED_GS)>>>(out4);
}

// round 15
// speedup vs baseline: 1.8266x; 1.0516x over previous
#include <cuda_runtime.h>

// Lyapunov spectrum for the Lorenz-Jacobian + row Gram-Schmidt reference.
//
// KEY IDENTITY: the reference's Q_t is row-orthonormal after every GS step,
// so the Gram matrix of M = (I+DT*J)Q_{t-1} is
//     S = M M^T = A (Q Q^T) A^T = A A^T,  A = I + DT*J(x,y,z),
// a pure function of the input sample (x,y,z). The outputs (log norms of the
// GS residuals) are functions of S only -> elementwise map over (T, B) plus
// a sum over T. Q never materializes.
//
// R8: 72.5 us (reduce latency-bound, grid=8).  R10: 41.7 us (reduce 8.6 us,
// grid of 64 blocks -> only 64/148 SMs, occ 11.5%).  R15 (= R11 resubmit):
// reduce re-tiled to 256 blocks x (8 tb-lanes x 32 g-slices), 8 independent
// float4 loads/thread, 32-way deterministic smem tree -- whole chip
// participates, scratch (8 MB) is L2-resident. Pass 1 frozen (~30 us vs
// ~25 us DRAM floor).

#define T_STEPS 2048
#define BATCH   8192
#define ROWS4   (BATCH / 4)           // 2048 float4 per component row
#define G_CHUNK 128
#define CHUNK_T (T_STEPS / G_CHUNK)   // 16 steps per chunk

#define DTf     0.01f
#define S11c    0.98010004f          // 0.99^2
#define S22c    0.94737780f          // A22^2
#define S12c    0.016666668f         // 0.99 - A22
#define T01ac   0.99388373f          // 0.9/sqrt(0.82)
#define T01bc   0.10932722f          // 0.099/sqrt(0.82)
#define T02ac   0.11043153f          // 0.1/sqrt(0.82)
#define LAM0c  -9.9225469f           // 0.5*ln(0.82)/DT

__device__ float4 g_partials[G_CHUNK * 2 * ROWS4];   // 8 MB scratch

__device__ __forceinline__ float frcp_approx(float v) {
    float r;
    asm("rcp.approx.f32 %0, %1;" : "=f"(r) : "f"(v));
    return r;
}

// squared GS residual norms (u11, v22) of one input sample
__device__ __forceinline__ void norms_from_sample(float x, float y, float z,
                                                  float &u11, float &v22)
{
    float c1 = fmaf(-DTf, z, 0.28f);       // DT*(28 - z)
    float cx = DTf * x;
    float cy = DTf * y;

    float cxsq = cx * cx;
    float s11  = fmaf(c1, c1, S11c + cxsq);
    float s12  = fmaf(c1, cy, S12c * cx);
    float s22  = fmaf(cy, cy, S22c + cxsq);

    // t0k = (q0' . m_k) with 1/sqrt(0.82) folded into the constants
    float t01 = fmaf(c1, T01ac, T01bc);
    float t02 = fmaf(cy, T01ac, T02ac * cx);

    u11 = fmaf(-t01, t01, s11);
    float u12 = fmaf(-t01, t02, s12);
    float u22 = fmaf(-t02, t02, s22);
    float w1  = frcp_approx(u11);
    v22 = fmaf(-u12 * u12, w1, u22);
}

// one time-step for 4 batch lanes
__device__ __forceinline__ void step4(const float4 &x, const float4 &y,
                                      const float4 &z,
                                      float4 &pl1, float4 &pl2)
{
    float u, v;
    norms_from_sample(x.x, y.x, z.x, u, v); pl1.x *= u; pl2.x *= v;
    norms_from_sample(x.y, y.y, z.y, u, v); pl1.y *= u; pl2.y *= v;
    norms_from_sample(x.z, y.z, z.z, u, v); pl1.z *= u; pl2.z *= v;
    norms_from_sample(x.w, y.w, z.w, u, v); pl1.w *= u; pl2.w *= v;
}

#define LOAD_GROUP(bx, by, bz, g)                                              \
    _Pragma("unroll")                                                          \
    for (int i = 0; i < 4; i++) {                                              \
        const float4* q = p + (size_t)((g) * 4 + i) * 3 * ROWS4;               \
        bx[i] = __ldcs(q);                                                     \
        by[i] = __ldcs(q + ROWS4);                                             \
        bz[i] = __ldcs(q + 2 * ROWS4);                                         \
    }

__global__ __launch_bounds__(256)
void lya_partials_kernel(const float4* __restrict__ traj4)
{
    const int tb    = blockIdx.x * 256 + threadIdx.x;   // 0 .. ROWS4-1
    const int chunk = blockIdx.y;
    const float4* p = traj4 + (size_t)chunk * CHUNK_T * 3 * ROWS4 + tb;

    float4 l1 = make_float4(0.f, 0.f, 0.f, 0.f);
    float4 l2 = make_float4(0.f, 0.f, 0.f, 0.f);

    float4 xa[4], ya[4], za[4], xb[4], yb[4], zb[4];
    const int NG = CHUNK_T / 4;                         // 4 groups of 4 steps

    LOAD_GROUP(xa, ya, za, 0)

    // steady state: branch-clean, double-buffered
#pragma unroll 1
    for (int g = 0; g < NG - 2; g += 2) {
        float4 pl1 = make_float4(1.f, 1.f, 1.f, 1.f);
        float4 pl2 = make_float4(1.f, 1.f, 1.f, 1.f);

        LOAD_GROUP(xb, yb, zb, g + 1)
#pragma unroll
        for (int i = 0; i < 4; i++) step4(xa[i], ya[i], za[i], pl1, pl2);

        LOAD_GROUP(xa, ya, za, g + 2)
#pragma unroll
        for (int i = 0; i < 4; i++) step4(xb[i], yb[i], zb[i], pl1, pl2);

        // one log per 8 steps per lane (product range ~[0.3, 1.5]^8, safe)
        l1.x += __log2f(pl1.x); l1.y += __log2f(pl1.y);
        l1.z += __log2f(pl1.z); l1.w += __log2f(pl1.w);
        l2.x += __log2f(pl2.x); l2.y += __log2f(pl2.y);
        l2.z += __log2f(pl2.z); l2.w += __log2f(pl2.w);
    }

    // epilogue: last two groups
    {
        float4 pl1 = make_float4(1.f, 1.f, 1.f, 1.f);
        float4 pl2 = make_float4(1.f, 1.f, 1.f, 1.f);

        LOAD_GROUP(xb, yb, zb, NG - 1)
#pragma unroll
        for (int i = 0; i < 4; i++) step4(xa[i], ya[i], za[i], pl1, pl2);
#pragma unroll
        for (int i = 0; i < 4; i++) step4(xb[i], yb[i], zb[i], pl1, pl2);

        l1.x += __log2f(pl1.x); l1.y += __log2f(pl1.y);
        l1.z += __log2f(pl1.z); l1.w += __log2f(pl1.w);
        l2.x += __log2f(pl2.x); l2.y += __log2f(pl2.y);
        l2.z += __log2f(pl2.z); l2.w += __log2f(pl2.w);
    }

    g_partials[(chunk * 2 + 0) * ROWS4 + tb] = l1;
    g_partials[(chunk * 2 + 1) * ROWS4 + tb] = l2;
}

// Reduce v3: 256 blocks x (8 tb-lanes x 32 g-slices). Each thread sums
// G_CHUNK/32 = 4 g-values for both components (8 independent float4 loads),
// then a 32-way smem tree per tb column. Fixed order -> deterministic.
#define RED_TB 8
#define RED_GS 32
__global__ __launch_bounds__(RED_TB * RED_GS)
void lya_reduce_kernel(float4* __restrict__ out4)
{
    __shared__ float4 sh1[RED_GS][RED_TB];
    __shared__ float4 sh2[RED_GS][RED_TB];

    const int lane = threadIdx.x;                    // tb within tile, 0..7
    const int ty   = threadIdx.y;                    // g slice, 0..31
    const int tb   = blockIdx.x * RED_TB + lane;

    float4 s1 = make_float4(0.f, 0.f, 0.f, 0.f);
    float4 s2 = make_float4(0.f, 0.f, 0.f, 0.f);

#pragma unroll
    for (int k = 0; k < G_CHUNK / RED_GS; k++) {     // 4 iterations
        int g = k * RED_GS + ty;
        float4 a = g_partials[(g * 2 + 0) * ROWS4 + tb];
        float4 b = g_partials[(g * 2 + 1) * ROWS4 + tb];
        s1.x += a.x; s1.y += a.y; s1.z += a.z; s1.w += a.w;
        s2.x += b.x; s2.y += b.y; s2.z += b.z; s2.w += b.w;
    }

    sh1[ty][lane] = s1;
    sh2[ty][lane] = s2;
    __syncthreads();

    // 32-way tree across ty (deterministic fixed order)
#pragma unroll
    for (int s = RED_GS / 2; s >= 1; s >>= 1) {
        if (ty < s) {
            float4 a1 = sh1[ty][lane], b1 = sh1[ty + s][lane];
            float4 a2 = sh2[ty][lane], b2 = sh2[ty + s][lane];
            sh1[ty][lane] = make_float4(a1.x + b1.x, a1.y + b1.y,
                                        a1.z + b1.z, a1.w + b1.w);
            sh2[ty][lane] = make_float4(a2.x + b2.x, a2.y + b2.y,
                                        a2.z + b2.z, a2.w + b2.w);
        }
        __syncthreads();
    }

    if (ty == 0) {
        float4 t1 = sh1[0][lane];
        float4 t2 = sh2[0][lane];
        // l = sum(log2 n^2) -> lambda = l * 0.5*ln2/(T*DT)
        const float scale = 0.5f * 0.69314718055994531f / (2048.0f * 0.01f);
        out4[tb] = make_float4(LAM0c, LAM0c, LAM0c, LAM0c);
        out4[ROWS4 + tb] = make_float4(t1.x * scale, t1.y * scale,
                                       t1.z * scale, t1.w * scale);
        out4[2 * ROWS4 + tb] = make_float4(t2.x * scale, t2.y * scale,
                                           t2.z * scale, t2.w * scale);
    }
}

extern "C" void kernel_launch(void* const* d_in, const int* in_sizes, int n_in,
                              void* d_out, int out_size)
{
    const float4* traj4 = (const float4*)d_in[0];
    float4* out4 = (float4*)d_out;
    (void)in_sizes; (void)n_in; (void)out_size;

    lya_partials_kernel<<<dim3(ROWS4 / 256, G_CHUNK), 256>>>(traj4);
    lya_reduce_kernel<<<ROWS4 / RED_TB, dim3(RED_TB, RED_GS)>>>(out4);
}

// round 16
// speedup vs baseline: 1.9260x; 1.0544x over previous
#include <cuda_runtime.h>

// Lyapunov spectrum for the Lorenz-Jacobian + row Gram-Schmidt reference.
//
// KEY IDENTITY: the reference's Q_t is row-orthonormal after every GS step,
// so the Gram matrix of M = (I+DT*J)Q_{t-1} is
//     S = M M^T = A (Q Q^T) A^T = A A^T,  A = I + DT*J(x,y,z),
// a pure function of the input sample (x,y,z). Outputs depend on S only ->
// elementwise map over (T, B) + sum over T. Q never materializes.
//
// R10: 41.7 us. R15: 39.7 us (reduce 6.75 us at grid=256 -- ramp/latency
// bound, not BW bound; pass 1 ~31 us ~= HBM floor). R16: shrink scratch 4x
// (G_CHUNK 128->32, 2 MB) so the ramp-bound reduce has 4x less to chew;
// keep pass-1 schedule via 64-thread blocks (7 blocks/SM, 1024 blocks =
// one full wave, ~14 warps/SM resident -- better latency cover than before).

#define T_STEPS 2048
#define BATCH   8192
#define ROWS4   (BATCH / 4)           // 2048 float4 per component row
#define G_CHUNK 32
#define CHUNK_T (T_STEPS / G_CHUNK)   // 64 steps per chunk

#define DTf     0.01f
#define S11c    0.98010004f          // 0.99^2
#define S22c    0.94737780f          // A22^2
#define S12c    0.016666668f         // 0.99 - A22
#define T01ac   0.99388373f          // 0.9/sqrt(0.82)
#define T01bc   0.10932722f          // 0.099/sqrt(0.82)
#define T02ac   0.11043153f          // 0.1/sqrt(0.82)
#define LAM0c  -9.9225469f           // 0.5*ln(0.82)/DT

__device__ float4 g_partials[G_CHUNK * 2 * ROWS4];   // 2 MB scratch

__device__ __forceinline__ float frcp_approx(float v) {
    float r;
    asm("rcp.approx.f32 %0, %1;" : "=f"(r) : "f"(v));
    return r;
}

// squared GS residual norms (u11, v22) of one input sample
__device__ __forceinline__ void norms_from_sample(float x, float y, float z,
                                                  float &u11, float &v22)
{
    float c1 = fmaf(-DTf, z, 0.28f);       // DT*(28 - z)
    float cx = DTf * x;
    float cy = DTf * y;

    float cxsq = cx * cx;
    float s11  = fmaf(c1, c1, S11c + cxsq);
    float s12  = fmaf(c1, cy, S12c * cx);
    float s22  = fmaf(cy, cy, S22c + cxsq);

    // t0k = (q0' . m_k) with 1/sqrt(0.82) folded into the constants
    float t01 = fmaf(c1, T01ac, T01bc);
    float t02 = fmaf(cy, T01ac, T02ac * cx);

    u11 = fmaf(-t01, t01, s11);
    float u12 = fmaf(-t01, t02, s12);
    float u22 = fmaf(-t02, t02, s22);
    float w1  = frcp_approx(u11);
    v22 = fmaf(-u12 * u12, w1, u22);
}

// one time-step for 4 batch lanes
__device__ __forceinline__ void step4(const float4 &x, const float4 &y,
                                      const float4 &z,
                                      float4 &pl1, float4 &pl2)
{
    float u, v;
    norms_from_sample(x.x, y.x, z.x, u, v); pl1.x *= u; pl2.x *= v;
    norms_from_sample(x.y, y.y, z.y, u, v); pl1.y *= u; pl2.y *= v;
    norms_from_sample(x.z, y.z, z.z, u, v); pl1.z *= u; pl2.z *= v;
    norms_from_sample(x.w, y.w, z.w, u, v); pl1.w *= u; pl2.w *= v;
}

#define LOAD_GROUP(bx, by, bz, g)                                              \
    _Pragma("unroll")                                                          \
    for (int i = 0; i < 4; i++) {                                              \
        const float4* q = p + (size_t)((g) * 4 + i) * 3 * ROWS4;               \
        bx[i] = __ldcs(q);                                                     \
        by[i] = __ldcs(q + ROWS4);                                             \
        bz[i] = __ldcs(q + 2 * ROWS4);                                         \
    }

// 64-thread blocks, cap regs so 7 blocks/SM fit: 1024 blocks = one wave.
__global__ __launch_bounds__(64, 7)
void lya_partials_kernel(const float4* __restrict__ traj4)
{
    const int tb    = blockIdx.x * 64 + threadIdx.x;    // 0 .. ROWS4-1
    const int chunk = blockIdx.y;
    const float4* p = traj4 + (size_t)chunk * CHUNK_T * 3 * ROWS4 + tb;

    float4 l1 = make_float4(0.f, 0.f, 0.f, 0.f);
    float4 l2 = make_float4(0.f, 0.f, 0.f, 0.f);

    float4 xa[4], ya[4], za[4], xb[4], yb[4], zb[4];
    const int NG = CHUNK_T / 4;                         // 16 groups of 4 steps

    LOAD_GROUP(xa, ya, za, 0)

    // steady state: branch-clean, double-buffered
#pragma unroll 1
    for (int g = 0; g < NG - 2; g += 2) {
        float4 pl1 = make_float4(1.f, 1.f, 1.f, 1.f);
        float4 pl2 = make_float4(1.f, 1.f, 1.f, 1.f);

        LOAD_GROUP(xb, yb, zb, g + 1)
#pragma unroll
        for (int i = 0; i < 4; i++) step4(xa[i], ya[i], za[i], pl1, pl2);

        LOAD_GROUP(xa, ya, za, g + 2)
#pragma unroll
        for (int i = 0; i < 4; i++) step4(xb[i], yb[i], zb[i], pl1, pl2);

        // one log per 8 steps per lane (product range ~[0.3, 1.5]^8, safe)
        l1.x += __log2f(pl1.x); l1.y += __log2f(pl1.y);
        l1.z += __log2f(pl1.z); l1.w += __log2f(pl1.w);
        l2.x += __log2f(pl2.x); l2.y += __log2f(pl2.y);
        l2.z += __log2f(pl2.z); l2.w += __log2f(pl2.w);
    }

    // epilogue: last two groups
    {
        float4 pl1 = make_float4(1.f, 1.f, 1.f, 1.f);
        float4 pl2 = make_float4(1.f, 1.f, 1.f, 1.f);

        LOAD_GROUP(xb, yb, zb, NG - 1)
#pragma unroll
        for (int i = 0; i < 4; i++) step4(xa[i], ya[i], za[i], pl1, pl2);
#pragma unroll
        for (int i = 0; i < 4; i++) step4(xb[i], yb[i], zb[i], pl1, pl2);

        l1.x += __log2f(pl1.x); l1.y += __log2f(pl1.y);
        l1.z += __log2f(pl1.z); l1.w += __log2f(pl1.w);
        l2.x += __log2f(pl2.x); l2.y += __log2f(pl2.y);
        l2.z += __log2f(pl2.z); l2.w += __log2f(pl2.w);
    }

    g_partials[(chunk * 2 + 0) * ROWS4 + tb] = l1;
    g_partials[(chunk * 2 + 1) * ROWS4 + tb] = l2;
}

// Reduce v4: 256 blocks x (8 tb-lanes x 32 g-slices). Each thread sums one
// g-value for both components (2 loads), then a 32-way smem tree per tb
// column. Fixed order -> deterministic. 2 MB scratch -> ramp-bound minimum.
#define RED_TB 8
#define RED_GS 32
__global__ __launch_bounds__(RED_TB * RED_GS)
void lya_reduce_kernel(float4* __restrict__ out4)
{
    __shared__ float4 sh1[RED_GS][RED_TB];
    __shared__ float4 sh2[RED_GS][RED_TB];

    const int lane = threadIdx.x;                    // tb within tile, 0..7
    const int ty   = threadIdx.y;                    // g slice, 0..31
    const int tb   = blockIdx.x * RED_TB + lane;

    float4 s1 = make_float4(0.f, 0.f, 0.f, 0.f);
    float4 s2 = make_float4(0.f, 0.f, 0.f, 0.f);

#pragma unroll
    for (int k = 0; k < G_CHUNK / RED_GS; k++) {     // 1 iteration
        int g = k * RED_GS + ty;
        float4 a = g_partials[(g * 2 + 0) * ROWS4 + tb];
        float4 b = g_partials[(g * 2 + 1) * ROWS4 + tb];
        s1.x += a.x; s1.y += a.y; s1.z += a.z; s1.w += a.w;
        s2.x += b.x; s2.y += b.y; s2.z += b.z; s2.w += b.w;
    }

    sh1[ty][lane] = s1;
    sh2[ty][lane] = s2;
    __syncthreads();

    // 32-way tree across ty (deterministic fixed order)
#pragma unroll
    for (int s = RED_GS / 2; s >= 1; s >>= 1) {
        if (ty < s) {
            float4 a1 = sh1[ty][lane], b1 = sh1[ty + s][lane];
            float4 a2 = sh2[ty][lane], b2 = sh2[ty + s][lane];
            sh1[ty][lane] = make_float4(a1.x + b1.x, a1.y + b1.y,
                                        a1.z + b1.z, a1.w + b1.w);
            sh2[ty][lane] = make_float4(a2.x + b2.x, a2.y + b2.y,
                                        a2.z + b2.z, a2.w + b2.w);
        }
        __syncthreads();
    }

    if (ty == 0) {
        float4 t1 = sh1[0][lane];
        float4 t2 = sh2[0][lane];
        // l = sum(log2 n^2) -> lambda = l * 0.5*ln2/(T*DT)
        const float scale = 0.5f * 0.69314718055994531f / (2048.0f * 0.01f);
        out4[tb] = make_float4(LAM0c, LAM0c, LAM0c, LAM0c);
        out4[ROWS4 + tb] = make_float4(t1.x * scale, t1.y * scale,
                                       t1.z * scale, t1.w * scale);
        out4[2 * ROWS4 + tb] = make_float4(t2.x * scale, t2.y * scale,
                                           t2.z * scale, t2.w * scale);
    }
}

extern "C" void kernel_launch(void* const* d_in, const int* in_sizes, int n_in,
                              void* d_out, int out_size)
{
    const float4* traj4 = (const float4*)d_in[0];
    float4* out4 = (float4*)d_out;
    (void)in_sizes; (void)n_in; (void)out_size;

    lya_partials_kernel<<<dim3(ROWS4 / 64, G_CHUNK), 64>>>(traj4);
    lya_reduce_kernel<<<ROWS4 / RED_TB, dim3(RED_TB, RED_GS)>>>(out4);
}